// round 4
// baseline (speedup 1.0000x reference)
#include <cuda_runtime.h>
#include <cuda_fp16.h>
#include <cstdint>

#define M_TOTAL 8192
#define N_TOTAL 4096
#define K_TOTAL 4096

// fp16 operands: A = fp16(x) [M][K], B = exact int4 values in fp16 [N][K]
__device__ __half g_A[(size_t)M_TOTAL * K_TOTAL];   // 64 MB
__device__ __half g_B[(size_t)N_TOTAL * K_TOTAL];   // 32 MB

// ---------------------------------------------------------------------------
// Prep kernels (streaming conversions, DRAM-bound, ~40us total)
// ---------------------------------------------------------------------------
__global__ void __launch_bounds__(256) prep_a_kernel(const float4* __restrict__ x4) {
    size_t i = (size_t)blockIdx.x * 256 + threadIdx.x;
    float4 v = x4[i];
    __half2* dst = (__half2*)g_A + i * 2;
    dst[0] = __floats2half2_rn(v.x, v.y);
    dst[1] = __floats2half2_rn(v.z, v.w);
}

__global__ void __launch_bounds__(256) prep_b_kernel(const int4* __restrict__ w4) {
    size_t i = (size_t)blockIdx.x * 256 + threadIdx.x;
    int4 q = w4[i];
    __half2* dst = (__half2*)g_B + i * 2;
    dst[0] = __floats2half2_rn((float)q.x, (float)q.y);
    dst[1] = __floats2half2_rn((float)q.z, (float)q.w);
}

// ---------------------------------------------------------------------------
// Helpers
// ---------------------------------------------------------------------------
__device__ __forceinline__ uint32_t smem_u32(const void* p) {
    uint32_t a;
    asm("{ .reg .u64 t; cvta.to.shared.u64 t, %1; cvt.u32.u64 %0, t; }" : "=r"(a) : "l"(p));
    return a;
}
__device__ __forceinline__ void cp_async16(uint32_t dst, const void* src) {
    asm volatile("cp.async.cg.shared.global [%0], [%1], 16;\n" :: "r"(dst), "l"(src));
}
__device__ __forceinline__ void ldm_x4(uint32_t& d0, uint32_t& d1, uint32_t& d2, uint32_t& d3, uint32_t a) {
    asm volatile("ldmatrix.sync.aligned.m8n8.x4.shared.b16 {%0,%1,%2,%3}, [%4];\n"
                 : "=r"(d0), "=r"(d1), "=r"(d2), "=r"(d3) : "r"(a));
}
__device__ __forceinline__ void mma16816(float* c, uint32_t a0, uint32_t a1, uint32_t a2, uint32_t a3,
                                         uint32_t b0, uint32_t b1) {
    asm volatile(
        "mma.sync.aligned.m16n8k16.row.col.f32.f16.f16.f32 "
        "{%0,%1,%2,%3}, {%4,%5,%6,%7}, {%8,%9}, {%0,%1,%2,%3};\n"
        : "+f"(c[0]), "+f"(c[1]), "+f"(c[2]), "+f"(c[3])
        : "r"(a0), "r"(a1), "r"(a2), "r"(a3), "r"(b0), "r"(b1));
}

// ---------------------------------------------------------------------------
// GEMM: CTA tile 128(M) x 256(N), BK=32, 4-stage cp.async ring.
// 8 warps = 2(M) x 4(N); warp tile 64 x 64. out = scale[n]*acc + bias[n].
// ---------------------------------------------------------------------------
#define BM 128
#define BN 256
#define BK 32
#define STAGES 4
#define NITER (K_TOTAL / BK)     // 128
#define A_STAGE 8192             // 128 rows x 64 B
#define B_STAGE 16384            // 256 rows x 64 B
#define SMEM_BYTES (STAGES * (A_STAGE + B_STAGE) + 1024)

__global__ void __launch_bounds__(256, 1)
gemm_kernel(const float* __restrict__ wscale, const float* __restrict__ bias,
            float* __restrict__ out)
{
    extern __shared__ char smem_raw[];
    const uint32_t base = (smem_u32(smem_raw) + 1023u) & ~1023u;
    const uint32_t sAb = base;                        // 4 x 8 KB
    const uint32_t sBb = base + STAGES * A_STAGE;     // 4 x 16 KB

    const int tid  = threadIdx.x;
    const int lane = tid & 31;
    const int warp = tid >> 5;
    const int wm   = warp >> 2;   // 0..1
    const int wn   = warp & 3;    // 0..3
    const int bm   = blockIdx.y * BM;
    const int bn   = blockIdx.x * BN;

    // ---- producer mapping
    // A: 512 chunks of 16B; thread t -> rows (t>>2), (t>>2)+64; chunk c = t&3
    const int ar = tid >> 2;      // 0..63
    const int ac = tid & 3;
    const int aswz = (ar >> 1) & 3;   // same for ar and ar+64
    const uint32_t aoff = (uint32_t)ar * 64 + (uint32_t)((ac ^ aswz) << 4);
    // B: 1024 chunks; thread t -> rows (t>>2) + {0,64,128,192}; chunk c = t&3
    const int br = tid >> 2;
    const int bc = tid & 3;
    const int bswz = (br >> 1) & 3;
    const uint32_t boff = (uint32_t)br * 64 + (uint32_t)((bc ^ bswz) << 4);

    const __half* gA = g_A + (size_t)(bm + ar) * K_TOTAL + ac * 8;
    const __half* gB = g_B + (size_t)(bn + br) * K_TOTAL + bc * 8;

    // ---- ldmatrix per-lane address precompute (x4 pattern for both A and B)
    // A frags: f in 0..3 covers m16 block (wm*64 + f*16)
    uint32_t a_rowoff[4], a_swz[4];
    const int kg = lane >> 4;   // chunk half-select within k-tile
    #pragma unroll
    for (int f = 0; f < 4; f++) {
        int row = wm * 64 + f * 16 + (lane & 15);
        a_rowoff[f] = (uint32_t)row * 64;
        a_swz[f]    = (row >> 1) & 3;
    }
    // B frags: g2 in 0..3 covers n16 block (wn*64 + g2*16)
    uint32_t b_rowoff[4], b_swz[4];
    #pragma unroll
    for (int g2 = 0; g2 < 4; g2++) {
        int row = wn * 64 + g2 * 16 + (lane & 15);
        b_rowoff[g2] = (uint32_t)row * 64;
        b_swz[g2]    = (row >> 1) & 3;
    }

    float acc[4][8][4];
    #pragma unroll
    for (int f = 0; f < 4; f++)
        #pragma unroll
        for (int g = 0; g < 8; g++)
            #pragma unroll
            for (int e = 0; e < 4; e++) acc[f][g][e] = 0.f;

    // ---- prologue: fill STAGES-1 slots
    #pragma unroll
    for (int s = 0; s < STAGES - 1; s++) {
        const uint32_t dA = sAb + s * A_STAGE;
        const uint32_t dB = sBb + s * B_STAGE;
        const int k = s * BK;
        cp_async16(dA + aoff,        gA + k);
        cp_async16(dA + aoff + 4096, gA + (size_t)64 * K_TOTAL + k);
        #pragma unroll
        for (int j = 0; j < 4; j++)
            cp_async16(dB + boff + j * 4096, gB + (size_t)(64 * j) * K_TOTAL + k);
        asm volatile("cp.async.commit_group;\n" ::: "memory");
    }

    for (int kt = 0; kt < NITER; kt++) {
        asm volatile("cp.async.wait_group %0;\n" :: "n"(STAGES - 2) : "memory");
        __syncthreads();

        // prefetch slot kt+STAGES-1
        if (kt + STAGES - 1 < NITER) {
            const int s = (kt + STAGES - 1) & (STAGES - 1);
            const int k = (kt + STAGES - 1) * BK;
            const uint32_t dA = sAb + s * A_STAGE;
            const uint32_t dB = sBb + s * B_STAGE;
            cp_async16(dA + aoff,        gA + k);
            cp_async16(dA + aoff + 4096, gA + (size_t)64 * K_TOTAL + k);
            #pragma unroll
            for (int j = 0; j < 4; j++)
                cp_async16(dB + boff + j * 4096, gB + (size_t)(64 * j) * K_TOTAL + k);
        }
        asm volatile("cp.async.commit_group;\n" ::: "memory");

        const int slot = kt & (STAGES - 1);
        const uint32_t sAbuf = sAb + slot * A_STAGE;
        const uint32_t sBbuf = sBb + slot * B_STAGE;

        #pragma unroll
        for (int ks = 0; ks < 2; ks++) {
            uint32_t a[4][4];
            #pragma unroll
            for (int f = 0; f < 4; f++) {
                uint32_t chunk = (uint32_t)(ks * 2 + kg) ^ a_swz[f];
                ldm_x4(a[f][0], a[f][1], a[f][2], a[f][3],
                       sAbuf + a_rowoff[f] + (chunk << 4));
            }
            uint32_t b[4][4];
            #pragma unroll
            for (int g2 = 0; g2 < 4; g2++) {
                uint32_t chunk = (uint32_t)(ks * 2 + kg) ^ b_swz[g2];
                ldm_x4(b[g2][0], b[g2][1], b[g2][2], b[g2][3],
                       sBbuf + b_rowoff[g2] + (chunk << 4));
            }
            #pragma unroll
            for (int f = 0; f < 4; f++) {
                #pragma unroll
                for (int g2 = 0; g2 < 4; g2++) {
                    // n8 group 0 of this n16: (r0, r2); group 1: (r1, r3)
                    mma16816(acc[f][g2 * 2 + 0], a[f][0], a[f][1], a[f][2], a[f][3],
                             b[g2][0], b[g2][2]);
                    mma16816(acc[f][g2 * 2 + 1], a[f][0], a[f][1], a[f][2], a[f][3],
                             b[g2][1], b[g2][3]);
                }
            }
        }
    }

    // ---- epilogue: out = scale[n]*acc + bias[n]
    const int mrow  = bm + wm * 64 + (lane >> 2);
    const int ncol0 = bn + wn * 64 + (lane & 3) * 2;

    float2 sc[8], bi[8];
    #pragma unroll
    for (int g = 0; g < 8; g++) {
        int col = ncol0 + g * 8;
        sc[g].x = wscale[col]; sc[g].y = wscale[col + 1];
        bi[g].x = bias[col];   bi[g].y = bias[col + 1];
    }
    #pragma unroll
    for (int f = 0; f < 4; f++) {
        int r0 = mrow + f * 16;
        #pragma unroll
        for (int g = 0; g < 8; g++) {
            int col = ncol0 + g * 8;
            float2 v0, v1;
            v0.x = acc[f][g][0] * sc[g].x + bi[g].x;
            v0.y = acc[f][g][1] * sc[g].y + bi[g].y;
            v1.x = acc[f][g][2] * sc[g].x + bi[g].x;
            v1.y = acc[f][g][3] * sc[g].y + bi[g].y;
            *(float2*)(out + (size_t)r0 * N_TOTAL + col)       = v0;
            *(float2*)(out + (size_t)(r0 + 8) * N_TOTAL + col) = v1;
        }
    }
}

// ---------------------------------------------------------------------------
extern "C" void kernel_launch(void* const* d_in, const int* in_sizes, int n_in,
                              void* d_out, int out_size) {
    const float* x      = (const float*)d_in[0];
    const int*   wq     = (const int*)d_in[1];
    const float* wscale = (const float*)d_in[2];
    const float* bias   = (const float*)d_in[3];
    float*       out    = (float*)d_out;

    prep_a_kernel<<<(M_TOTAL * (size_t)K_TOTAL / 4) / 256, 256>>>((const float4*)x);
    prep_b_kernel<<<(N_TOTAL * (size_t)K_TOTAL / 4) / 256, 256>>>((const int4*)wq);

    cudaFuncSetAttribute(gemm_kernel, cudaFuncAttributeMaxDynamicSharedMemorySize, SMEM_BYTES);
    dim3 grid(N_TOTAL / BN, M_TOTAL / BM);   // (16, 64) — N fastest for B reuse in L2
    gemm_kernel<<<grid, 256, SMEM_BYTES>>>(wscale, bias, out);
}

// round 5
// speedup vs baseline: 1.1465x; 1.1465x over previous
#include <cuda_runtime.h>
#include <cuda_fp16.h>
#include <cstdint>

#define M_TOTAL 8192
#define N_TOTAL 4096
#define K_TOTAL 4096

// fp16 operands: A = fp16(x) [M][K], B = exact int4 values in fp16 [N][K]
__device__ __half g_A[(size_t)M_TOTAL * K_TOTAL];   // 64 MB
__device__ __half g_B[(size_t)N_TOTAL * K_TOTAL];   // 32 MB

// ---------------------------------------------------------------------------
// Prep kernels (streaming conversions, DRAM-bound, ~45us total)
// ---------------------------------------------------------------------------
__global__ void __launch_bounds__(256) prep_a_kernel(const float4* __restrict__ x4) {
    size_t i = (size_t)blockIdx.x * 256 + threadIdx.x;
    float4 v = x4[i];
    __half2* dst = (__half2*)g_A + i * 2;
    dst[0] = __floats2half2_rn(v.x, v.y);
    dst[1] = __floats2half2_rn(v.z, v.w);
}

__global__ void __launch_bounds__(256) prep_b_kernel(const int4* __restrict__ w4) {
    size_t i = (size_t)blockIdx.x * 256 + threadIdx.x;
    int4 q = w4[i];
    __half2* dst = (__half2*)g_B + i * 2;
    dst[0] = __floats2half2_rn((float)q.x, (float)q.y);
    dst[1] = __floats2half2_rn((float)q.z, (float)q.w);
}

// ---------------------------------------------------------------------------
// Helpers
// ---------------------------------------------------------------------------
__device__ __forceinline__ uint32_t smem_u32(const void* p) {
    uint32_t a;
    asm("{ .reg .u64 t; cvta.to.shared.u64 t, %1; cvt.u32.u64 %0, t; }" : "=r"(a) : "l"(p));
    return a;
}
__device__ __forceinline__ void cp_async16(uint32_t dst, const void* src) {
    asm volatile("cp.async.cg.shared.global [%0], [%1], 16;\n" :: "r"(dst), "l"(src));
}
__device__ __forceinline__ void ldm_x4(uint32_t& d0, uint32_t& d1, uint32_t& d2, uint32_t& d3, uint32_t a) {
    asm volatile("ldmatrix.sync.aligned.m8n8.x4.shared.b16 {%0,%1,%2,%3}, [%4];\n"
                 : "=r"(d0), "=r"(d1), "=r"(d2), "=r"(d3) : "r"(a));
}
__device__ __forceinline__ void ldm_x2(uint32_t& d0, uint32_t& d1, uint32_t a) {
    asm volatile("ldmatrix.sync.aligned.m8n8.x2.shared.b16 {%0,%1}, [%2];\n"
                 : "=r"(d0), "=r"(d1) : "r"(a));
}
__device__ __forceinline__ void mma16816(float* c, const uint32_t* a, const uint32_t* b) {
    asm volatile(
        "mma.sync.aligned.m16n8k16.row.col.f32.f16.f16.f32 "
        "{%0,%1,%2,%3}, {%4,%5,%6,%7}, {%8,%9}, {%0,%1,%2,%3};\n"
        : "+f"(c[0]), "+f"(c[1]), "+f"(c[2]), "+f"(c[3])
        : "r"(a[0]), "r"(a[1]), "r"(a[2]), "r"(a[3]), "r"(b[0]), "r"(b[1]));
}

// ---------------------------------------------------------------------------
// GEMM: CTA tile 128x128, BK=32, 4-stage cp.async ring, 8 warps (2M x 4N),
// warp tile 64x32. 2 CTAs/SM (65KB smem request + reg cap 128).
// ---------------------------------------------------------------------------
#define BK 32
#define STAGES 4
#define NITER (K_TOTAL / BK)     // 128
#define STAGE 8192               // 128 rows x 64 B
#define SMEM_BYTES (2 * STAGES * STAGE + 1024)   // 66560

__global__ void __launch_bounds__(256, 2)
gemm_kernel(const float* __restrict__ wscale, const float* __restrict__ bias,
            float* __restrict__ out)
{
    extern __shared__ char smem_raw[];
    const uint32_t base = (smem_u32(smem_raw) + 1023u) & ~1023u;
    const uint32_t sAbase = base;                      // 4 x 8KB
    const uint32_t sBbase = base + STAGES * STAGE;     // 4 x 8KB

    const int tid  = threadIdx.x;
    const int lane = tid & 31;
    const int warp = tid >> 5;
    const int wm   = warp >> 2;   // 0..1
    const int wn   = warp & 3;    // 0..3
    const int bm   = blockIdx.y * 128;
    const int bn   = blockIdx.x * 128;

    // producer mapping: 2 x 16B chunks per thread per operand
    const int r  = tid >> 2;          // 0..63
    const int c  = tid & 3;
    const int swz = (r >> 1) & 3;
    const uint32_t soff = (uint32_t)r * 64 + (uint32_t)((c ^ swz) << 4);

    const __half* gA = g_A + (size_t)(bm + r) * K_TOTAL + c * 8;
    const __half* gB = g_B + (size_t)(bn + r) * K_TOTAL + c * 8;

    // ldmatrix per-lane address precompute
    uint32_t a_rowoff[4], a_swz[4];
    const int a_kg = lane >> 4;
    #pragma unroll
    for (int f = 0; f < 4; f++) {
        int row = wm * 64 + f * 16 + (lane & 15);
        a_rowoff[f] = (uint32_t)row * 64;
        a_swz[f]    = (row >> 1) & 3;
    }
    uint32_t b_rowoff[4], b_swz[4];
    const int b_kg = (lane >> 3) & 1;
    #pragma unroll
    for (int g = 0; g < 4; g++) {
        int row = wn * 32 + g * 8 + (lane & 7);
        b_rowoff[g] = (uint32_t)row * 64;
        b_swz[g]    = (row >> 1) & 3;
    }

    float acc[4][4][4];
    #pragma unroll
    for (int f = 0; f < 4; f++)
        #pragma unroll
        for (int g = 0; g < 4; g++)
            #pragma unroll
            for (int e = 0; e < 4; e++) acc[f][g][e] = 0.f;

    // prologue: fill STAGES-1 slots
    #pragma unroll
    for (int s = 0; s < STAGES - 1; s++) {
        const uint32_t dA = sAbase + s * STAGE;
        const uint32_t dB = sBbase + s * STAGE;
        const int k = s * BK;
        cp_async16(dA + soff,        gA + k);
        cp_async16(dA + soff + 4096, gA + (size_t)64 * K_TOTAL + k);
        cp_async16(dB + soff,        gB + k);
        cp_async16(dB + soff + 4096, gB + (size_t)64 * K_TOTAL + k);
        asm volatile("cp.async.commit_group;\n" ::: "memory");
    }

    for (int kt = 0; kt < NITER; kt++) {
        asm volatile("cp.async.wait_group %0;\n" :: "n"(STAGES - 2) : "memory");
        __syncthreads();

        // prefetch slot kt+STAGES-1
        if (kt + STAGES - 1 < NITER) {
            const int s = (kt + STAGES - 1) & (STAGES - 1);
            const int k = (kt + STAGES - 1) * BK;
            const uint32_t dA = sAbase + s * STAGE;
            const uint32_t dB = sBbase + s * STAGE;
            cp_async16(dA + soff,        gA + k);
            cp_async16(dA + soff + 4096, gA + (size_t)64 * K_TOTAL + k);
            cp_async16(dB + soff,        gB + k);
            cp_async16(dB + soff + 4096, gB + (size_t)64 * K_TOTAL + k);
        }
        asm volatile("cp.async.commit_group;\n" ::: "memory");

        const int slot = kt & (STAGES - 1);
        const uint32_t sAbuf = sAbase + slot * STAGE;
        const uint32_t sBbuf = sBbase + slot * STAGE;

        #pragma unroll
        for (int ks = 0; ks < 2; ks++) {
            uint32_t a[4][4];
            #pragma unroll
            for (int f = 0; f < 4; f++) {
                uint32_t chunk = (uint32_t)(ks * 2 + a_kg) ^ a_swz[f];
                ldm_x4(a[f][0], a[f][1], a[f][2], a[f][3],
                       sAbuf + a_rowoff[f] + (chunk << 4));
            }
            uint32_t b[4][2];
            #pragma unroll
            for (int g = 0; g < 4; g++) {
                uint32_t chunk = (uint32_t)(ks * 2 + b_kg) ^ b_swz[g];
                ldm_x2(b[g][0], b[g][1], sBbuf + b_rowoff[g] + (chunk << 4));
            }
            #pragma unroll
            for (int f = 0; f < 4; f++)
                #pragma unroll
                for (int g = 0; g < 4; g++)
                    mma16816(acc[f][g], a[f], b[g]);
        }
    }

    // epilogue: out = scale[n]*acc + bias[n] (scale/bias loaded inline — L1/L2 hot)
    const int mrow  = bm + wm * 64 + (lane >> 2);
    const int ncol0 = bn + wn * 32 + (lane & 3) * 2;

    #pragma unroll
    for (int f = 0; f < 4; f++) {
        int r0 = mrow + f * 16;
        #pragma unroll
        for (int g = 0; g < 4; g++) {
            int col = ncol0 + g * 8;
            float sx = wscale[col], sy = wscale[col + 1];
            float bx = bias[col],   by = bias[col + 1];
            float2 v0, v1;
            v0.x = acc[f][g][0] * sx + bx;
            v0.y = acc[f][g][1] * sy + by;
            v1.x = acc[f][g][2] * sx + bx;
            v1.y = acc[f][g][3] * sy + by;
            *(float2*)(out + (size_t)r0 * N_TOTAL + col)       = v0;
            *(float2*)(out + (size_t)(r0 + 8) * N_TOTAL + col) = v1;
        }
    }
}

// ---------------------------------------------------------------------------
extern "C" void kernel_launch(void* const* d_in, const int* in_sizes, int n_in,
                              void* d_out, int out_size) {
    const float* x      = (const float*)d_in[0];
    const int*   wq     = (const int*)d_in[1];
    const float* wscale = (const float*)d_in[2];
    const float* bias   = (const float*)d_in[3];
    float*       out    = (float*)d_out;

    prep_a_kernel<<<(M_TOTAL * (size_t)K_TOTAL / 4) / 256, 256>>>((const float4*)x);
    prep_b_kernel<<<(N_TOTAL * (size_t)K_TOTAL / 4) / 256, 256>>>((const int4*)wq);

    cudaFuncSetAttribute(gemm_kernel, cudaFuncAttributeMaxDynamicSharedMemorySize, SMEM_BYTES);
    dim3 grid(N_TOTAL / 128, M_TOTAL / 128);   // (32, 64) — N fastest for B reuse in L2
    gemm_kernel<<<grid, 256, SMEM_BYTES>>>(wscale, bias, out);
}

// round 6
// speedup vs baseline: 1.1503x; 1.0033x over previous
#include <cuda_runtime.h>
#include <cuda_fp16.h>
#include <cstdint>

#define M_TOTAL 8192
#define N_TOTAL 4096
#define K_TOTAL 4096

// fp16 operands: A = fp16(x) [M][K], B = exact int4 values in fp16 [N][K]
__device__ __half g_A[(size_t)M_TOTAL * K_TOTAL];   // 64 MB
__device__ __half g_B[(size_t)N_TOTAL * K_TOTAL];   // 32 MB

// ---------------------------------------------------------------------------
// Fused prep kernel (A-convert blocks then B-convert blocks; both DRAM-bound).
// Fusing makes each harness replay exactly 2 launches, so ncu (-s 5) profiles
// the GEMM instead of the prep.
// ---------------------------------------------------------------------------
#define NA_CHUNKS ((size_t)M_TOTAL * K_TOTAL / 4)   // 8388608 float4 chunks
#define NB_CHUNKS ((size_t)N_TOTAL * K_TOTAL / 4)   // 4194304 int4 chunks

__global__ void __launch_bounds__(256) prep_kernel(const float4* __restrict__ x4,
                                                   const int4* __restrict__ w4) {
    size_t i = (size_t)blockIdx.x * 256 + threadIdx.x;
    if (i < NA_CHUNKS) {
        float4 v = x4[i];
        __half2* dst = (__half2*)g_A + i * 2;
        dst[0] = __floats2half2_rn(v.x, v.y);
        dst[1] = __floats2half2_rn(v.z, v.w);
    } else {
        size_t j = i - NA_CHUNKS;
        int4 q = w4[j];
        __half2* dst = (__half2*)g_B + j * 2;
        dst[0] = __floats2half2_rn((float)q.x, (float)q.y);
        dst[1] = __floats2half2_rn((float)q.z, (float)q.w);
    }
}

// ---------------------------------------------------------------------------
// Helpers
// ---------------------------------------------------------------------------
__device__ __forceinline__ uint32_t smem_u32(const void* p) {
    uint32_t a;
    asm("{ .reg .u64 t; cvta.to.shared.u64 t, %1; cvt.u32.u64 %0, t; }" : "=r"(a) : "l"(p));
    return a;
}
__device__ __forceinline__ void cp_async16(uint32_t dst, const void* src) {
    asm volatile("cp.async.cg.shared.global [%0], [%1], 16;\n" :: "r"(dst), "l"(src));
}
__device__ __forceinline__ void ldm_x4(uint32_t& d0, uint32_t& d1, uint32_t& d2, uint32_t& d3, uint32_t a) {
    asm volatile("ldmatrix.sync.aligned.m8n8.x4.shared.b16 {%0,%1,%2,%3}, [%4];\n"
                 : "=r"(d0), "=r"(d1), "=r"(d2), "=r"(d3) : "r"(a));
}
__device__ __forceinline__ void mma16816(float* c, uint32_t a0, uint32_t a1, uint32_t a2, uint32_t a3,
                                         uint32_t b0, uint32_t b1) {
    asm volatile(
        "mma.sync.aligned.m16n8k16.row.col.f32.f16.f16.f32 "
        "{%0,%1,%2,%3}, {%4,%5,%6,%7}, {%8,%9}, {%0,%1,%2,%3};\n"
        : "+f"(c[0]), "+f"(c[1]), "+f"(c[2]), "+f"(c[3])
        : "r"(a0), "r"(a1), "r"(a2), "r"(a3), "r"(b0), "r"(b1));
}

// ---------------------------------------------------------------------------
// GEMM: CTA tile 128x128, 128 threads = 4 warps (2M x 2N), warp tile 64x64.
// BK=32, 4-stage cp.async ring. ~190 regs/thread, 66KB smem -> 2 CTAs/SM
// (8 warps/SM across 2 independent CTAs; no reg cap, no spills).
// ---------------------------------------------------------------------------
#define BK 32
#define STAGES 4
#define NITER (K_TOTAL / BK)     // 128
#define A_STAGE 8192             // 128 rows x 64 B
#define B_STAGE 8192
#define SMEM_BYTES (STAGES * (A_STAGE + B_STAGE) + 1024)   // 66560

__global__ void __launch_bounds__(128)
gemm_kernel(const float* __restrict__ wscale, const float* __restrict__ bias,
            float* __restrict__ out)
{
    extern __shared__ char smem_raw[];
    const uint32_t base = (smem_u32(smem_raw) + 1023u) & ~1023u;
    const uint32_t sAb = base;                        // 4 x 8 KB
    const uint32_t sBb = base + STAGES * A_STAGE;     // 4 x 8 KB

    const int tid  = threadIdx.x;
    const int lane = tid & 31;
    const int warp = tid >> 5;    // 0..3
    const int wm   = warp >> 1;   // 0..1
    const int wn   = warp & 1;    // 0..1
    const int bm   = blockIdx.y * 128;
    const int bn   = blockIdx.x * 128;

    // ---- producer mapping: 4 x 16B chunks per thread per operand per stage
    // thread t -> rows (t>>2) + {0,32,64,96}; k-chunk c = t&3 (16B each)
    const int pr  = tid >> 2;          // 0..31
    const int pc  = tid & 3;
    const int psw = (pr >> 1) & 3;     // invariant under +32 row steps
    const uint32_t soff = (uint32_t)pr * 64 + (uint32_t)((pc ^ psw) << 4);

    const __half* gA = g_A + (size_t)(bm + pr) * K_TOTAL + pc * 8;
    const __half* gB = g_B + (size_t)(bn + pr) * K_TOTAL + pc * 8;

    // ---- ldmatrix per-lane address precompute (x4 for both A and B)
    const int kg = lane >> 4;          // k8-half select
    uint32_t a_off[4], a_sw[4];
    #pragma unroll
    for (int f = 0; f < 4; f++) {
        int row = wm * 64 + f * 16 + (lane & 15);
        a_off[f] = (uint32_t)row * 64;
        a_sw[f]  = (row >> 1) & 3;
    }
    uint32_t b_off[4], b_sw[4];
    #pragma unroll
    for (int g2 = 0; g2 < 4; g2++) {
        int row = wn * 64 + g2 * 16 + (lane & 15);
        b_off[g2] = (uint32_t)row * 64;
        b_sw[g2]  = (row >> 1) & 3;
    }

    float acc[4][8][4];
    #pragma unroll
    for (int f = 0; f < 4; f++)
        #pragma unroll
        for (int g = 0; g < 8; g++)
            #pragma unroll
            for (int e = 0; e < 4; e++) acc[f][g][e] = 0.f;

    // ---- prologue: fill STAGES-1 slots
    #pragma unroll
    for (int s = 0; s < STAGES - 1; s++) {
        const uint32_t dA = sAb + s * A_STAGE;
        const uint32_t dB = sBb + s * B_STAGE;
        const int k = s * BK;
        #pragma unroll
        for (int j = 0; j < 4; j++) {
            cp_async16(dA + soff + j * 2048, gA + (size_t)(32 * j) * K_TOTAL + k);
            cp_async16(dB + soff + j * 2048, gB + (size_t)(32 * j) * K_TOTAL + k);
        }
        asm volatile("cp.async.commit_group;\n" ::: "memory");
    }

    for (int kt = 0; kt < NITER; kt++) {
        asm volatile("cp.async.wait_group %0;\n" :: "n"(STAGES - 2) : "memory");
        __syncthreads();

        // prefetch slot kt+STAGES-1
        if (kt + STAGES - 1 < NITER) {
            const int s = (kt + STAGES - 1) & (STAGES - 1);
            const int k = (kt + STAGES - 1) * BK;
            const uint32_t dA = sAb + s * A_STAGE;
            const uint32_t dB = sBb + s * B_STAGE;
            #pragma unroll
            for (int j = 0; j < 4; j++) {
                cp_async16(dA + soff + j * 2048, gA + (size_t)(32 * j) * K_TOTAL + k);
                cp_async16(dB + soff + j * 2048, gB + (size_t)(32 * j) * K_TOTAL + k);
            }
        }
        asm volatile("cp.async.commit_group;\n" ::: "memory");

        const int slot = kt & (STAGES - 1);
        const uint32_t sAbuf = sAb + slot * A_STAGE;
        const uint32_t sBbuf = sBb + slot * B_STAGE;

        #pragma unroll
        for (int ks = 0; ks < 2; ks++) {
            uint32_t a[4][4];
            #pragma unroll
            for (int f = 0; f < 4; f++) {
                uint32_t chunk = (uint32_t)(ks * 2 + kg) ^ a_sw[f];
                ldm_x4(a[f][0], a[f][1], a[f][2], a[f][3],
                       sAbuf + a_off[f] + (chunk << 4));
            }
            uint32_t b[4][4];
            #pragma unroll
            for (int g2 = 0; g2 < 4; g2++) {
                uint32_t chunk = (uint32_t)(ks * 2 + kg) ^ b_sw[g2];
                ldm_x4(b[g2][0], b[g2][1], b[g2][2], b[g2][3],
                       sBbuf + b_off[g2] + (chunk << 4));
            }
            #pragma unroll
            for (int f = 0; f < 4; f++) {
                #pragma unroll
                for (int g2 = 0; g2 < 4; g2++) {
                    mma16816(acc[f][g2 * 2 + 0], a[f][0], a[f][1], a[f][2], a[f][3],
                             b[g2][0], b[g2][2]);
                    mma16816(acc[f][g2 * 2 + 1], a[f][0], a[f][1], a[f][2], a[f][3],
                             b[g2][1], b[g2][3]);
                }
            }
        }
    }

    // ---- epilogue: out = scale[n]*acc + bias[n]
    const int mrow  = bm + wm * 64 + (lane >> 2);
    const int ncol0 = bn + wn * 64 + (lane & 3) * 2;

    #pragma unroll
    for (int f = 0; f < 4; f++) {
        int r0 = mrow + f * 16;
        #pragma unroll
        for (int g = 0; g < 8; g++) {
            int col = ncol0 + g * 8;
            float sx = wscale[col], sy = wscale[col + 1];
            float bx = bias[col],   by = bias[col + 1];
            float2 v0, v1;
            v0.x = acc[f][g][0] * sx + bx;
            v0.y = acc[f][g][1] * sy + by;
            v1.x = acc[f][g][2] * sx + bx;
            v1.y = acc[f][g][3] * sy + by;
            *(float2*)(out + (size_t)r0 * N_TOTAL + col)       = v0;
            *(float2*)(out + (size_t)(r0 + 8) * N_TOTAL + col) = v1;
        }
    }
}

// ---------------------------------------------------------------------------
extern "C" void kernel_launch(void* const* d_in, const int* in_sizes, int n_in,
                              void* d_out, int out_size) {
    const float* x      = (const float*)d_in[0];
    const int*   wq     = (const int*)d_in[1];
    const float* wscale = (const float*)d_in[2];
    const float* bias   = (const float*)d_in[3];
    float*       out    = (float*)d_out;

    prep_kernel<<<(NA_CHUNKS + NB_CHUNKS) / 256, 256>>>((const float4*)x, (const int4*)wq);

    cudaFuncSetAttribute(gemm_kernel, cudaFuncAttributeMaxDynamicSharedMemorySize, SMEM_BYTES);
    dim3 grid(N_TOTAL / 128, M_TOTAL / 128);   // (32, 64) — N fastest for B reuse in L2
    gemm_kernel<<<grid, 128, SMEM_BYTES>>>(wscale, bias, out);
}

// round 7
// speedup vs baseline: 1.2277x; 1.0673x over previous
#include <cuda_runtime.h>
#include <cuda_fp16.h>
#include <cstdint>

#define M_TOTAL 8192
#define N_TOTAL 4096
#define K_TOTAL 4096

// fp16 operands: A = fp16(x) [M][K], B = exact int4 values in fp16 [N][K]
__device__ __half g_A[(size_t)M_TOTAL * K_TOTAL];   // 64 MB
__device__ __half g_B[(size_t)N_TOTAL * K_TOTAL];   // 32 MB

// ---------------------------------------------------------------------------
// Fused prep kernel: A-convert chunks first, then B-convert chunks.
// ---------------------------------------------------------------------------
#define NA_CHUNKS ((size_t)M_TOTAL * K_TOTAL / 4)
#define NB_CHUNKS ((size_t)N_TOTAL * K_TOTAL / 4)

__global__ void __launch_bounds__(256) prep_kernel(const float4* __restrict__ x4,
                                                   const int4* __restrict__ w4) {
    size_t i = (size_t)blockIdx.x * 256 + threadIdx.x;
    if (i < NA_CHUNKS) {
        float4 v = x4[i];
        __half2* dst = (__half2*)g_A + i * 2;
        dst[0] = __floats2half2_rn(v.x, v.y);
        dst[1] = __floats2half2_rn(v.z, v.w);
    } else {
        size_t j = i - NA_CHUNKS;
        int4 q = w4[j];
        __half2* dst = (__half2*)g_B + j * 2;
        dst[0] = __floats2half2_rn((float)q.x, (float)q.y);
        dst[1] = __floats2half2_rn((float)q.z, (float)q.w);
    }
}

// ---------------------------------------------------------------------------
// Helpers
// ---------------------------------------------------------------------------
__device__ __forceinline__ uint32_t smem_u32(const void* p) {
    uint32_t a;
    asm("{ .reg .u64 t; cvta.to.shared.u64 t, %1; cvt.u32.u64 %0, t; }" : "=r"(a) : "l"(p));
    return a;
}
__device__ __forceinline__ void cp_async16(uint32_t dst, const void* src) {
    asm volatile("cp.async.cg.shared.global [%0], [%1], 16;\n" :: "r"(dst), "l"(src));
}
__device__ __forceinline__ void ldm_x4(uint32_t& d0, uint32_t& d1, uint32_t& d2, uint32_t& d3, uint32_t a) {
    asm volatile("ldmatrix.sync.aligned.m8n8.x4.shared.b16 {%0,%1,%2,%3}, [%4];\n"
                 : "=r"(d0), "=r"(d1), "=r"(d2), "=r"(d3) : "r"(a));
}
__device__ __forceinline__ void ldm_x2(uint32_t& d0, uint32_t& d1, uint32_t a) {
    asm volatile("ldmatrix.sync.aligned.m8n8.x2.shared.b16 {%0,%1}, [%2];\n"
                 : "=r"(d0), "=r"(d1) : "r"(a));
}
__device__ __forceinline__ void mma16816(float* c, const uint32_t* a, const uint32_t* b) {
    asm volatile(
        "mma.sync.aligned.m16n8k16.row.col.f32.f16.f16.f32 "
        "{%0,%1,%2,%3}, {%4,%5,%6,%7}, {%8,%9}, {%0,%1,%2,%3};\n"
        : "+f"(c[0]), "+f"(c[1]), "+f"(c[2]), "+f"(c[3])
        : "r"(a[0]), "r"(a[1]), "r"(a[2]), "r"(a[3]), "r"(b[0]), "r"(b[1]));
}

// ---------------------------------------------------------------------------
// GEMM: CTA 128x128, BK=64, 3-stage cp.async ring, 256 thr = 8 warps (2Mx4N),
// warp tile 64x32 (the proven 96%-of-ceiling fragment schedule).
// SMEM rows are 128 B (full k-tile), SW128 swizzle: chunk ^= (row & 7).
// ---------------------------------------------------------------------------
#define BK 64
#define STAGES 3
#define NITER (K_TOTAL / BK)     // 64
#define OP_STAGE 16384           // 128 rows x 128 B (per operand)
#define SMEM_BYTES (2 * STAGES * OP_STAGE + 1024)   // 99328

__global__ void __launch_bounds__(256)
gemm_kernel(const float* __restrict__ wscale, const float* __restrict__ bias,
            float* __restrict__ out)
{
    extern __shared__ char smem_raw[];
    const uint32_t base = (smem_u32(smem_raw) + 1023u) & ~1023u;
    const uint32_t sAb = base;                          // 3 x 16 KB
    const uint32_t sBb = base + STAGES * OP_STAGE;      // 3 x 16 KB

    const int tid  = threadIdx.x;
    const int lane = tid & 31;
    const int warp = tid >> 5;
    const int wm   = warp >> 2;   // 0..1
    const int wn   = warp & 3;    // 0..3
    const int bm   = blockIdx.y * 128;
    const int bn   = blockIdx.x * 128;

    // ---- producer mapping: per operand per stage, 4 rows x 16B per thread
    // thread t -> rows (t>>3) + {0,32,64,96}; k-chunk kc = t&7 (16B each)
    const int pr = tid >> 3;           // 0..31
    const int kc = tid & 7;
    const uint32_t pswz = (uint32_t)(pr & 7);   // invariant under +32
    uint32_t soff[4];
    #pragma unroll
    for (int j = 0; j < 4; j++)
        soff[j] = (uint32_t)(pr + 32 * j) * 128 + (((uint32_t)kc ^ pswz) << 4);

    const __half* gA = g_A + (size_t)(bm + pr) * K_TOTAL + kc * 8;
    const __half* gB = g_B + (size_t)(bn + pr) * K_TOTAL + kc * 8;

    // ---- ldmatrix per-lane address precompute
    // A frags (x4, m16k16): f in 0..3 -> m row wm*64 + f*16 + (lane&15)
    const int a_kg = lane >> 4;              // k8-half
    uint32_t a_off[4], a_sw[4];
    #pragma unroll
    for (int f = 0; f < 4; f++) {
        int row = wm * 64 + f * 16 + (lane & 15);
        a_off[f] = (uint32_t)row * 128;
        a_sw[f]  = (uint32_t)(row & 7);
    }
    // B frags (x2, n8k16): g in 0..3 -> n row wn*32 + g*8 + (lane&7)
    const int b_kg = (lane >> 3) & 1;
    uint32_t b_off[4], b_sw[4];
    #pragma unroll
    for (int g = 0; g < 4; g++) {
        int row = wn * 32 + g * 8 + (lane & 7);
        b_off[g] = (uint32_t)row * 128;
        b_sw[g]  = (uint32_t)(row & 7);
    }

    float acc[4][4][4];
    #pragma unroll
    for (int f = 0; f < 4; f++)
        #pragma unroll
        for (int g = 0; g < 4; g++)
            #pragma unroll
            for (int e = 0; e < 4; e++) acc[f][g][e] = 0.f;

    // ---- prologue: fill STAGES-1 slots
    #pragma unroll
    for (int s = 0; s < STAGES - 1; s++) {
        const uint32_t dA = sAb + s * OP_STAGE;
        const uint32_t dB = sBb + s * OP_STAGE;
        const int k = s * BK;
        #pragma unroll
        for (int j = 0; j < 4; j++) {
            cp_async16(dA + soff[j], gA + (size_t)(32 * j) * K_TOTAL + k);
            cp_async16(dB + soff[j], gB + (size_t)(32 * j) * K_TOTAL + k);
        }
        asm volatile("cp.async.commit_group;\n" ::: "memory");
    }

    for (int kt = 0; kt < NITER; kt++) {
        asm volatile("cp.async.wait_group %0;\n" :: "n"(STAGES - 2) : "memory");
        __syncthreads();

        // prefetch slot kt+STAGES-1
        if (kt + STAGES - 1 < NITER) {
            const int s = (kt + STAGES - 1) % STAGES;
            const int k = (kt + STAGES - 1) * BK;
            const uint32_t dA = sAb + s * OP_STAGE;
            const uint32_t dB = sBb + s * OP_STAGE;
            #pragma unroll
            for (int j = 0; j < 4; j++) {
                cp_async16(dA + soff[j], gA + (size_t)(32 * j) * K_TOTAL + k);
                cp_async16(dB + soff[j], gB + (size_t)(32 * j) * K_TOTAL + k);
            }
        }
        asm volatile("cp.async.commit_group;\n" ::: "memory");

        const int slot = kt % STAGES;
        const uint32_t sAbuf = sAb + slot * OP_STAGE;
        const uint32_t sBbuf = sBb + slot * OP_STAGE;

        #pragma unroll
        for (int ks = 0; ks < 4; ks++) {        // 4 x k16 within the 64-k tile
            uint32_t a[4][4];
            #pragma unroll
            for (int f = 0; f < 4; f++) {
                uint32_t chunk = (uint32_t)(ks * 2 + a_kg) ^ a_sw[f];
                ldm_x4(a[f][0], a[f][1], a[f][2], a[f][3],
                       sAbuf + a_off[f] + (chunk << 4));
            }
            uint32_t b[4][2];
            #pragma unroll
            for (int g = 0; g < 4; g++) {
                uint32_t chunk = (uint32_t)(ks * 2 + b_kg) ^ b_sw[g];
                ldm_x2(b[g][0], b[g][1], sBbuf + b_off[g] + (chunk << 4));
            }
            #pragma unroll
            for (int f = 0; f < 4; f++)
                #pragma unroll
                for (int g = 0; g < 4; g++)
                    mma16816(acc[f][g], a[f], b[g]);
        }
    }

    // ---- epilogue: out = scale[n]*acc + bias[n]
    const int mrow  = bm + wm * 64 + (lane >> 2);
    const int ncol0 = bn + wn * 32 + (lane & 3) * 2;

    #pragma unroll
    for (int f = 0; f < 4; f++) {
        int r0 = mrow + f * 16;
        #pragma unroll
        for (int g = 0; g < 4; g++) {
            int col = ncol0 + g * 8;
            float sx = wscale[col], sy = wscale[col + 1];
            float bx = bias[col],   by = bias[col + 1];
            float2 v0, v1;
            v0.x = acc[f][g][0] * sx + bx;
            v0.y = acc[f][g][1] * sy + by;
            v1.x = acc[f][g][2] * sx + bx;
            v1.y = acc[f][g][3] * sy + by;
            *(float2*)(out + (size_t)r0 * N_TOTAL + col)       = v0;
            *(float2*)(out + (size_t)(r0 + 8) * N_TOTAL + col) = v1;
        }
    }
}

// ---------------------------------------------------------------------------
extern "C" void kernel_launch(void* const* d_in, const int* in_sizes, int n_in,
                              void* d_out, int out_size) {
    const float* x      = (const float*)d_in[0];
    const int*   wq     = (const int*)d_in[1];
    const float* wscale = (const float*)d_in[2];
    const float* bias   = (const float*)d_in[3];
    float*       out    = (float*)d_out;

    prep_kernel<<<(NA_CHUNKS + NB_CHUNKS) / 256, 256>>>((const float4*)x, (const int4*)wq);

    cudaFuncSetAttribute(gemm_kernel, cudaFuncAttributeMaxDynamicSharedMemorySize, SMEM_BYTES);
    dim3 grid(N_TOTAL / 128, M_TOTAL / 128);   // N fastest for B reuse in L2
    gemm_kernel<<<grid, 256, SMEM_BYTES>>>(wscale, bias, out);
}